// round 10
// baseline (speedup 1.0000x reference)
#include <cuda_runtime.h>

#define RG 8
#define LC 64
#define NP 4096
#define SD 1024

// ---------------- device scratch ----------------
__device__ float g_centers[RG * LC * SD];
__device__ float g_c2[RG * LC];
__device__ float g_x2[RG * NP];
__device__ int   g_labels[RG * NP];

// ---------------- f32x2 helpers (each lane = independent IEEE rn fp32) ------
__device__ __forceinline__ unsigned long long fma2(unsigned long long a,
                                                   unsigned long long b,
                                                   unsigned long long c) {
    unsigned long long d;
    asm("fma.rn.f32x2 %0, %1, %2, %3;" : "=l"(d) : "l"(a), "l"(b), "l"(c));
    return d;
}
__device__ __forceinline__ void unpack2(unsigned long long v, float &lo, float &hi) {
    asm("mov.b64 {%0, %1}, %2;" : "=f"(lo), "=f"(hi) : "l"(v));
}

// ---------------- threefry2x32 (20 rounds) ----------------
__device__ __forceinline__ unsigned rotl32(unsigned v, int s) {
    return (v << s) | (v >> (32 - s));
}
__device__ __forceinline__ void threefry2x32(unsigned k0, unsigned k1,
                                             unsigned &x0, unsigned &x1) {
    unsigned ks0 = k0, ks1 = k1, ks2 = k0 ^ k1 ^ 0x1BD11BDAu;
    x0 += ks0; x1 += ks1;
#define TF_R(r) { x0 += x1; x1 = rotl32(x1, (r)); x1 ^= x0; }
    TF_R(13) TF_R(15) TF_R(26) TF_R(6)   x0 += ks1; x1 += ks2 + 1u;
    TF_R(17) TF_R(29) TF_R(16) TF_R(24)  x0 += ks2; x1 += ks0 + 2u;
    TF_R(13) TF_R(15) TF_R(26) TF_R(6)   x0 += ks0; x1 += ks1 + 3u;
    TF_R(17) TF_R(29) TF_R(16) TF_R(24)  x0 += ks1; x1 += ks2 + 4u;
    TF_R(13) TF_R(15) TF_R(26) TF_R(6)   x0 += ks2; x1 += ks0 + 5u;
#undef TF_R
}

__device__ void bitonic4096(unsigned long long *kc, int tid) {
    for (int k = 2; k <= 4096; k <<= 1) {
        for (int j = k >> 1; j > 0; j >>= 1) {
            for (int t = tid; t < 4096; t += 1024) {
                int ixj = t ^ j;
                if (ixj > t) {
                    unsigned long long a = kc[t], b = kc[ixj];
                    bool up = ((t & k) == 0);
                    if ((a > b) == up) { kc[t] = b; kc[ixj] = a; }
                }
            }
            __syncthreads();
        }
    }
}

// init + gather fused: jax.random.permutation(split(key(42),8)[r],4096)[:64],
// then centers[r][l] = pts[r][idx[l]] and flat-sequential c2 (64 parallel chains).
__global__ __launch_bounds__(1024) void init_gather_kernel(const float *__restrict__ x) {
    __shared__ unsigned long long kc[4096];   // 32 KB
    __shared__ unsigned perm1[4096];          // 16 KB
    __shared__ int idx64[64];
    int r = blockIdx.x, tid = threadIdx.x;

    unsigned K0 = 0u, K1 = (unsigned)r;
    threefry2x32(0u, 42u, K0, K1);
    unsigned n0 = 0u, n1 = 0u;   threefry2x32(K0, K1, n0, n1);
    unsigned s1a = 0u, s1b = 1u; threefry2x32(K0, K1, s1a, s1b);
    unsigned s2a = 0u, s2b = 1u; threefry2x32(n0, n1, s2a, s2b);

    for (int i = tid; i < 4096; i += 1024) {
        unsigned a = 0u, b = (unsigned)i;
        threefry2x32(s1a, s1b, a, b);
        kc[i] = ((unsigned long long)(a ^ b) << 32) | (unsigned)i;
    }
    __syncthreads();
    bitonic4096(kc, tid);
    for (int i = tid; i < 4096; i += 1024)
        perm1[i] = (unsigned)(kc[i] & 0xffffffffu);
    __syncthreads();

    for (int i = tid; i < 4096; i += 1024) {
        unsigned a = 0u, b = (unsigned)i;
        threefry2x32(s2a, s2b, a, b);
        kc[i] = ((unsigned long long)(a ^ b) << 32) | (unsigned)i;
    }
    __syncthreads();
    bitonic4096(kc, tid);
    if (tid < 64)
        idx64[tid] = (int)perm1[(unsigned)(kc[tid] & 0xffffffffu)];
    __syncthreads();

    // gather 64 rows -> g_centers (float4, all 1024 threads)
    for (int i = tid; i < 64 * 256; i += 1024) {
        int l = i >> 8, q = i & 255;
        const float4 *src = (const float4 *)(x + ((size_t)(r * NP + idx64[l])) * SD);
        float4 *dst = (float4 *)(g_centers + (((size_t)(r * 64 + l)) << 10));
        dst[q] = src[q];
    }
    // c2: 64 parallel flat-sequential chains (identical order to before)
    if (tid < 64) {
        const float *src = x + ((size_t)(r * NP + idx64[tid])) * SD;
        float ss = 0.f;
#pragma unroll 16
        for (int d = 0; d < SD; ++d)
            ss = __fadd_rn(ss, __fmul_rn(src[d], src[d]));
        g_c2[r * 64 + tid] = ss;
    }
}

// ---------------- x2: 8 parallel flat-sequential chains per block ----------------
#define X2ROW 1036
__global__ __launch_bounds__(128) void x2_kernel(const float *__restrict__ x) {
    __shared__ __align__(16) float s[8 * X2ROW];
    int pb = blockIdx.x * 8;
    const float4 *src = (const float4 *)(x + (size_t)pb * SD);
    for (int i = threadIdx.x; i < 8 * (SD / 4); i += 128) {
        int p = i >> 8, q = i & 255;
        *(float4 *)&s[p * X2ROW + q * 4] = src[p * 256 + q];
    }
    __syncthreads();
    if (threadIdx.x < 8) {
        const float *row = &s[threadIdx.x * X2ROW];
        float ss = 0.f;
#pragma unroll 8
        for (int d = 0; d < SD; ++d)
            ss = __fadd_rn(ss, __fmul_rn(row[d], row[d]));
        g_x2[pb + threadIdx.x] = ss;
    }
}

// ---------------- assign: argmin_l fl(fl(x2+c2[l]) - 2*dot) ----------------
// 512 threads; block = 256 pts x 64 ctrs; thread tile 4pt(2 f32x2 pairs) x 8ctr.
// Centers pre-duplicated (c,c) in smem; KCH=16.
#define KCH 16
#define BPT 256
__global__ __launch_bounds__(512) void assign_kernel(const float *__restrict__ x,
                                                     float *__restrict__ out,
                                                     int write_out) {
    __shared__ __align__(16) float pT[2][KCH][BPT];    // 32 KB
    __shared__ __align__(16) float cTd[2][KCH][128];   // 16 KB
    __shared__ float rv[8][BPT];                       // 8 KB
    __shared__ int   ri[8][BPT];                       // 8 KB

    int bx = blockIdx.x;
    int r = bx >> 4, tile = bx & 15;
    int pbase = tile * BPT;
    const float *pts = x + ((size_t)r * NP) * SD;
    const float *ctr = g_centers + ((size_t)r * LC) * SD;
    int tid = threadIdx.x;
    int pc = tid & 63;
    int cc = tid >> 6;

    bool pload = tid < 256;
    bool cload = (tid >= 256) && (tid < 384);
    int ci = tid - 256;
    int sc_c = ci & 63, sc_h = (ci >> 6) & 1;
    const float *prow = pts + (size_t)(pbase + (pload ? tid : 0)) * SD;
    const float *crow = ctr + (size_t)(cload ? sc_c : 0) * SD + sc_h * 8;

    unsigned long long acc[2][8];
#pragma unroll
    for (int i = 0; i < 2; i++)
#pragma unroll
        for (int j = 0; j < 8; j++) acc[i][j] = 0ull;

    float4 sp[4], sc0, sc1;
    if (pload) {
#pragma unroll
        for (int q = 0; q < 4; q++) sp[q] = *(const float4 *)(prow + q * 4);
    }
    if (cload) { sc0 = *(const float4 *)(crow); sc1 = *(const float4 *)(crow + 4); }
    if (pload) {
#pragma unroll
        for (int q = 0; q < 4; q++) {
            pT[0][q * 4 + 0][tid] = sp[q].x; pT[0][q * 4 + 1][tid] = sp[q].y;
            pT[0][q * 4 + 2][tid] = sp[q].z; pT[0][q * 4 + 3][tid] = sp[q].w;
        }
    }
    if (cload) {
        int kb = sc_h * 8, c2i = sc_c * 2;
        cTd[0][kb + 0][c2i] = sc0.x; cTd[0][kb + 0][c2i + 1] = sc0.x;
        cTd[0][kb + 1][c2i] = sc0.y; cTd[0][kb + 1][c2i + 1] = sc0.y;
        cTd[0][kb + 2][c2i] = sc0.z; cTd[0][kb + 2][c2i + 1] = sc0.z;
        cTd[0][kb + 3][c2i] = sc0.w; cTd[0][kb + 3][c2i + 1] = sc0.w;
        cTd[0][kb + 4][c2i] = sc1.x; cTd[0][kb + 4][c2i + 1] = sc1.x;
        cTd[0][kb + 5][c2i] = sc1.y; cTd[0][kb + 5][c2i + 1] = sc1.y;
        cTd[0][kb + 6][c2i] = sc1.z; cTd[0][kb + 6][c2i + 1] = sc1.z;
        cTd[0][kb + 7][c2i] = sc1.w; cTd[0][kb + 7][c2i + 1] = sc1.w;
    }
    if (pload) {
#pragma unroll
        for (int q = 0; q < 4; q++) sp[q] = *(const float4 *)(prow + KCH + q * 4);
    }
    if (cload) { sc0 = *(const float4 *)(crow + KCH); sc1 = *(const float4 *)(crow + KCH + 4); }
    __syncthreads();

    const int NCHUNK = SD / KCH;   // 64
    for (int c = 0; c < NCHUNK; ++c) {
        int cur = c & 1;
        if (c + 1 < NCHUNK) {
            int nb = cur ^ 1;
            if (pload) {
#pragma unroll
                for (int q = 0; q < 4; q++) {
                    pT[nb][q * 4 + 0][tid] = sp[q].x; pT[nb][q * 4 + 1][tid] = sp[q].y;
                    pT[nb][q * 4 + 2][tid] = sp[q].z; pT[nb][q * 4 + 3][tid] = sp[q].w;
                }
            }
            if (cload) {
                int kb = sc_h * 8, c2i = sc_c * 2;
                cTd[nb][kb + 0][c2i] = sc0.x; cTd[nb][kb + 0][c2i + 1] = sc0.x;
                cTd[nb][kb + 1][c2i] = sc0.y; cTd[nb][kb + 1][c2i + 1] = sc0.y;
                cTd[nb][kb + 2][c2i] = sc0.z; cTd[nb][kb + 2][c2i + 1] = sc0.z;
                cTd[nb][kb + 3][c2i] = sc0.w; cTd[nb][kb + 3][c2i + 1] = sc0.w;
                cTd[nb][kb + 4][c2i] = sc1.x; cTd[nb][kb + 4][c2i + 1] = sc1.x;
                cTd[nb][kb + 5][c2i] = sc1.y; cTd[nb][kb + 5][c2i + 1] = sc1.y;
                cTd[nb][kb + 6][c2i] = sc1.z; cTd[nb][kb + 6][c2i + 1] = sc1.z;
                cTd[nb][kb + 7][c2i] = sc1.w; cTd[nb][kb + 7][c2i + 1] = sc1.w;
            }
            if (c + 2 < NCHUNK) {
                int k0 = (c + 2) * KCH;
                if (pload) {
#pragma unroll
                    for (int q = 0; q < 4; q++)
                        sp[q] = *(const float4 *)(prow + k0 + q * 4);
                }
                if (cload) {
                    sc0 = *(const float4 *)(crow + k0);
                    sc1 = *(const float4 *)(crow + k0 + 4);
                }
            }
        }
#pragma unroll
        for (int kk = 0; kk < KCH; ++kk) {
            ulonglong2 pa  = *(const ulonglong2 *)&pT[cur][kk][pc * 4];
            ulonglong2 c01 = *(const ulonglong2 *)&cTd[cur][kk][cc * 16 + 0];
            ulonglong2 c23 = *(const ulonglong2 *)&cTd[cur][kk][cc * 16 + 4];
            ulonglong2 c45 = *(const ulonglong2 *)&cTd[cur][kk][cc * 16 + 8];
            ulonglong2 c67 = *(const ulonglong2 *)&cTd[cur][kk][cc * 16 + 12];
            unsigned long long pp[2] = {pa.x, pa.y};
            unsigned long long cd[8] = {c01.x, c01.y, c23.x, c23.y,
                                        c45.x, c45.y, c67.x, c67.y};
#pragma unroll
            for (int i = 0; i < 2; i++)
#pragma unroll
                for (int j = 0; j < 8; j++)
                    acc[i][j] = fma2(pp[i], cd[j], acc[i][j]);
        }
        __syncthreads();
    }

    float c2s[8];
#pragma unroll
    for (int j = 0; j < 8; j++) c2s[j] = g_c2[r * 64 + cc * 8 + j];
#pragma unroll
    for (int e = 0; e < 4; ++e) {
        int pair = e >> 1, lane = e & 1;
        int p = pc * 4 + e;
        float x2v = g_x2[r * NP + pbase + p];
        float dots[8];
#pragma unroll
        for (int j = 0; j < 8; j++) {
            float lo, hi;
            unpack2(acc[pair][j], lo, hi);
            dots[j] = lane ? hi : lo;
        }
        float bv;
        int bj = 0;
        {
            float sS = __fadd_rn(x2v, c2s[0]);
            bv = __fadd_rn(sS, __fmul_rn(-2.f, dots[0]));
        }
#pragma unroll
        for (int j = 1; j < 8; j++) {
            float sS = __fadd_rn(x2v, c2s[j]);
            float v = __fadd_rn(sS, __fmul_rn(-2.f, dots[j]));
            if (v < bv) { bv = v; bj = j; }   // strict < keeps first-min
        }
        rv[cc][p] = bv;
        ri[cc][p] = cc * 8 + bj;
    }
    __syncthreads();
    if (tid < 256) {   // ascending cc keeps lowest center index on ties
        float bv = rv[0][tid];
        int bi = ri[0][tid];
#pragma unroll
        for (int g = 1; g < 8; ++g) {
            float v = rv[g][tid];
            if (v < bv) { bv = v; bi = ri[g][tid]; }
        }
        g_labels[r * NP + pbase + tid] = bi;
        ri[0][tid] = bi;   // stash for fused output
    }
    if (write_out) {
        __syncthreads();
        int w = tid >> 5, lane = tid & 31;
#pragma unroll
        for (int i = 0; i < 16; ++i) {
            int row = w * 16 + i;
            int lb = ri[0][row];
            const float4 *src = (const float4 *)(g_centers + (((size_t)(r * 64 + lb)) << 10));
            float4 *dst = (float4 *)(out + (((size_t)(r * NP + pbase + row)) << 10));
#pragma unroll
            for (int j = 0; j < 8; ++j)
                dst[lane + 32 * j] = src[lane + 32 * j];
        }
    }
}

// -------- fused update: per-cluster stable compaction + sums + finalize --------
// block = (r, cluster c); 512 threads, 2 dims each (float2).
// Member order: thread chunks of 8 ascending -> exact ascending-n.
// c2: squares precomputed elementwise (exact), thread0 chains pure fadds.
__global__ __launch_bounds__(512) void update_kernel(const float *__restrict__ x) {
    __shared__ int   lab[NP];     // 16 KB
    __shared__ int   mem[NP];     // 16 KB
    __shared__ int   cntT[512];
    __shared__ float s2[SD];      // 4 KB (squares)
    int b = blockIdx.x;           // r*64 + c
    int r = b >> 6, c = b & 63, tid = threadIdx.x;

    const int4 *lsrc = (const int4 *)&g_labels[r * NP];
    for (int i = tid; i < NP / 4; i += 512) ((int4 *)lab)[i] = lsrc[i];
    __syncthreads();

    int base = tid * 8, k = 0;
#pragma unroll
    for (int i = 0; i < 8; ++i) k += (lab[base + i] == c);
    cntT[tid] = k;
    __syncthreads();
    int pre = 0, tot = 0;
    for (int i = 0; i < 512; ++i) {
        int v = cntT[i];
        if (i < tid) pre += v;
        tot += v;
    }
    int pos = pre;
#pragma unroll
    for (int i = 0; i < 8; ++i) {
        int n = base + i;
        if (lab[n] == c) mem[pos++] = n;
    }
    __syncthreads();

    int cnt = tot;
    size_t cbase = ((size_t)b) << 10;
    float ax = 0.f, ay = 0.f;
    const float *xr = x + ((size_t)r * NP) * SD;
    int d = tid * 2;
#pragma unroll 16
    for (int m = 0; m < cnt; ++m) {
        float2 v = *(const float2 *)(xr + ((size_t)mem[m]) * SD + d);
        ax = __fadd_rn(ax, v.x); ay = __fadd_rn(ay, v.y);
    }
    float fcnt = (float)cnt;
    float o0, o1;
    if (cnt > 0) {
        o0 = __fdiv_rn(ax, fcnt); o1 = __fdiv_rn(ay, fcnt);
    } else {
        o0 = g_centers[cbase + d + 0]; o1 = g_centers[cbase + d + 1];
    }
    g_centers[cbase + d + 0] = o0; g_centers[cbase + d + 1] = o1;
    s2[d + 0] = __fmul_rn(o0, o0); s2[d + 1] = __fmul_rn(o1, o1);
    __syncthreads();
    if (tid == 0) {
        float ss = 0.f;
#pragma unroll 8
        for (int dd = 0; dd < SD; ++dd) ss = __fadd_rn(ss, s2[dd]);
        g_c2[b] = ss;
    }
}

extern "C" void kernel_launch(void* const* d_in, const int* in_sizes, int n_in,
                              void* d_out, int out_size) {
    const float *x = (const float *)d_in[0];
    float *out = (float *)d_out;
    (void)in_sizes; (void)n_in; (void)out_size;

    init_gather_kernel<<<RG, 1024>>>(x);      // launch 1
    x2_kernel<<<RG * NP / 8, 128>>>(x);       // launch 2
    for (int it = 0; it < 10; ++it) {
        assign_kernel<<<RG * 16, 512>>>(x, out, 0);   // launch 3, 5, ...
        update_kernel<<<RG * LC, 512>>>(x);           // launch 4 <- profiled
    }
    assign_kernel<<<RG * 16, 512>>>(x, out, 1);
}

// round 11
// speedup vs baseline: 1.2509x; 1.2509x over previous
#include <cuda_runtime.h>

#define RG 8
#define LC 64
#define NP 4096
#define SD 1024

// ---------------- device scratch ----------------
__device__ float g_centers[RG * LC * SD];
__device__ float g_c2[RG * LC];
__device__ float g_x2[RG * NP];
__device__ int   g_labels[RG * NP];

// ---------------- f32x2 helpers (each lane = independent IEEE rn fp32) ------
__device__ __forceinline__ unsigned long long fma2(unsigned long long a,
                                                   unsigned long long b,
                                                   unsigned long long c) {
    unsigned long long d;
    asm("fma.rn.f32x2 %0, %1, %2, %3;" : "=l"(d) : "l"(a), "l"(b), "l"(c));
    return d;
}
__device__ __forceinline__ void unpack2(unsigned long long v, float &lo, float &hi) {
    asm("mov.b64 {%0, %1}, %2;" : "=f"(lo), "=f"(hi) : "l"(v));
}

// ---------------- threefry2x32 (20 rounds) ----------------
__device__ __forceinline__ unsigned rotl32(unsigned v, int s) {
    return (v << s) | (v >> (32 - s));
}
__device__ __forceinline__ void threefry2x32(unsigned k0, unsigned k1,
                                             unsigned &x0, unsigned &x1) {
    unsigned ks0 = k0, ks1 = k1, ks2 = k0 ^ k1 ^ 0x1BD11BDAu;
    x0 += ks0; x1 += ks1;
#define TF_R(r) { x0 += x1; x1 = rotl32(x1, (r)); x1 ^= x0; }
    TF_R(13) TF_R(15) TF_R(26) TF_R(6)   x0 += ks1; x1 += ks2 + 1u;
    TF_R(17) TF_R(29) TF_R(16) TF_R(24)  x0 += ks2; x1 += ks0 + 2u;
    TF_R(13) TF_R(15) TF_R(26) TF_R(6)   x0 += ks0; x1 += ks1 + 3u;
    TF_R(17) TF_R(29) TF_R(16) TF_R(24)  x0 += ks1; x1 += ks2 + 4u;
    TF_R(13) TF_R(15) TF_R(26) TF_R(6)   x0 += ks2; x1 += ks0 + 5u;
#undef TF_R
}

__device__ void bitonic4096(unsigned long long *kc, int tid) {
    for (int k = 2; k <= 4096; k <<= 1) {
        for (int j = k >> 1; j > 0; j >>= 1) {
            for (int t = tid; t < 4096; t += 1024) {
                int ixj = t ^ j;
                if (ixj > t) {
                    unsigned long long a = kc[t], b = kc[ixj];
                    bool up = ((t & k) == 0);
                    if ((a > b) == up) { kc[t] = b; kc[ixj] = a; }
                }
            }
            __syncthreads();
        }
    }
}

// init + gather fused
__global__ __launch_bounds__(1024) void init_gather_kernel(const float *__restrict__ x) {
    __shared__ unsigned long long kc[4096];
    __shared__ unsigned perm1[4096];
    __shared__ int idx64[64];
    int r = blockIdx.x, tid = threadIdx.x;

    unsigned K0 = 0u, K1 = (unsigned)r;
    threefry2x32(0u, 42u, K0, K1);
    unsigned n0 = 0u, n1 = 0u;   threefry2x32(K0, K1, n0, n1);
    unsigned s1a = 0u, s1b = 1u; threefry2x32(K0, K1, s1a, s1b);
    unsigned s2a = 0u, s2b = 1u; threefry2x32(n0, n1, s2a, s2b);

    for (int i = tid; i < 4096; i += 1024) {
        unsigned a = 0u, b = (unsigned)i;
        threefry2x32(s1a, s1b, a, b);
        kc[i] = ((unsigned long long)(a ^ b) << 32) | (unsigned)i;
    }
    __syncthreads();
    bitonic4096(kc, tid);
    for (int i = tid; i < 4096; i += 1024)
        perm1[i] = (unsigned)(kc[i] & 0xffffffffu);
    __syncthreads();

    for (int i = tid; i < 4096; i += 1024) {
        unsigned a = 0u, b = (unsigned)i;
        threefry2x32(s2a, s2b, a, b);
        kc[i] = ((unsigned long long)(a ^ b) << 32) | (unsigned)i;
    }
    __syncthreads();
    bitonic4096(kc, tid);
    if (tid < 64)
        idx64[tid] = (int)perm1[(unsigned)(kc[tid] & 0xffffffffu)];
    __syncthreads();

    for (int i = tid; i < 64 * 256; i += 1024) {
        int l = i >> 8, q = i & 255;
        const float4 *src = (const float4 *)(x + ((size_t)(r * NP + idx64[l])) * SD);
        float4 *dst = (float4 *)(g_centers + (((size_t)(r * 64 + l)) << 10));
        dst[q] = src[q];
    }
    if (tid < 64) {
        const float *src = x + ((size_t)(r * NP + idx64[tid])) * SD;
        float ss = 0.f;
#pragma unroll 16
        for (int d = 0; d < SD; ++d)
            ss = __fadd_rn(ss, __fmul_rn(src[d], src[d]));
        g_c2[r * 64 + tid] = ss;
    }
}

// ---------------- x2: 8 parallel flat-sequential chains per block ----------------
#define X2ROW 1036
__global__ __launch_bounds__(128) void x2_kernel(const float *__restrict__ x) {
    __shared__ __align__(16) float s[8 * X2ROW];
    int pb = blockIdx.x * 8;
    const float4 *src = (const float4 *)(x + (size_t)pb * SD);
    for (int i = threadIdx.x; i < 8 * (SD / 4); i += 128) {
        int p = i >> 8, q = i & 255;
        *(float4 *)&s[p * X2ROW + q * 4] = src[p * 256 + q];
    }
    __syncthreads();
    if (threadIdx.x < 8) {
        const float *row = &s[threadIdx.x * X2ROW];
        float ss = 0.f;
#pragma unroll 8
        for (int d = 0; d < SD; ++d)
            ss = __fadd_rn(ss, __fmul_rn(row[d], row[d]));
        g_x2[pb + threadIdx.x] = ss;
    }
}

// ---------------- assign (unchanged from R9/R10 passing version) ----------------
#define KCH 16
#define BPT 256
__global__ __launch_bounds__(512) void assign_kernel(const float *__restrict__ x,
                                                     float *__restrict__ out,
                                                     int write_out) {
    __shared__ __align__(16) float pT[2][KCH][BPT];
    __shared__ __align__(16) float cTd[2][KCH][128];
    __shared__ float rv[8][BPT];
    __shared__ int   ri[8][BPT];

    int bx = blockIdx.x;
    int r = bx >> 4, tile = bx & 15;
    int pbase = tile * BPT;
    const float *pts = x + ((size_t)r * NP) * SD;
    const float *ctr = g_centers + ((size_t)r * LC) * SD;
    int tid = threadIdx.x;
    int pc = tid & 63;
    int cc = tid >> 6;

    bool pload = tid < 256;
    bool cload = (tid >= 256) && (tid < 384);
    int ci = tid - 256;
    int sc_c = ci & 63, sc_h = (ci >> 6) & 1;
    const float *prow = pts + (size_t)(pbase + (pload ? tid : 0)) * SD;
    const float *crow = ctr + (size_t)(cload ? sc_c : 0) * SD + sc_h * 8;

    unsigned long long acc[2][8];
#pragma unroll
    for (int i = 0; i < 2; i++)
#pragma unroll
        for (int j = 0; j < 8; j++) acc[i][j] = 0ull;

    float4 sp[4], sc0, sc1;
    if (pload) {
#pragma unroll
        for (int q = 0; q < 4; q++) sp[q] = *(const float4 *)(prow + q * 4);
    }
    if (cload) { sc0 = *(const float4 *)(crow); sc1 = *(const float4 *)(crow + 4); }
    if (pload) {
#pragma unroll
        for (int q = 0; q < 4; q++) {
            pT[0][q * 4 + 0][tid] = sp[q].x; pT[0][q * 4 + 1][tid] = sp[q].y;
            pT[0][q * 4 + 2][tid] = sp[q].z; pT[0][q * 4 + 3][tid] = sp[q].w;
        }
    }
    if (cload) {
        int kb = sc_h * 8, c2i = sc_c * 2;
        cTd[0][kb + 0][c2i] = sc0.x; cTd[0][kb + 0][c2i + 1] = sc0.x;
        cTd[0][kb + 1][c2i] = sc0.y; cTd[0][kb + 1][c2i + 1] = sc0.y;
        cTd[0][kb + 2][c2i] = sc0.z; cTd[0][kb + 2][c2i + 1] = sc0.z;
        cTd[0][kb + 3][c2i] = sc0.w; cTd[0][kb + 3][c2i + 1] = sc0.w;
        cTd[0][kb + 4][c2i] = sc1.x; cTd[0][kb + 4][c2i + 1] = sc1.x;
        cTd[0][kb + 5][c2i] = sc1.y; cTd[0][kb + 5][c2i + 1] = sc1.y;
        cTd[0][kb + 6][c2i] = sc1.z; cTd[0][kb + 6][c2i + 1] = sc1.z;
        cTd[0][kb + 7][c2i] = sc1.w; cTd[0][kb + 7][c2i + 1] = sc1.w;
    }
    if (pload) {
#pragma unroll
        for (int q = 0; q < 4; q++) sp[q] = *(const float4 *)(prow + KCH + q * 4);
    }
    if (cload) { sc0 = *(const float4 *)(crow + KCH); sc1 = *(const float4 *)(crow + KCH + 4); }
    __syncthreads();

    const int NCHUNK = SD / KCH;
    for (int c = 0; c < NCHUNK; ++c) {
        int cur = c & 1;
        if (c + 1 < NCHUNK) {
            int nb = cur ^ 1;
            if (pload) {
#pragma unroll
                for (int q = 0; q < 4; q++) {
                    pT[nb][q * 4 + 0][tid] = sp[q].x; pT[nb][q * 4 + 1][tid] = sp[q].y;
                    pT[nb][q * 4 + 2][tid] = sp[q].z; pT[nb][q * 4 + 3][tid] = sp[q].w;
                }
            }
            if (cload) {
                int kb = sc_h * 8, c2i = sc_c * 2;
                cTd[nb][kb + 0][c2i] = sc0.x; cTd[nb][kb + 0][c2i + 1] = sc0.x;
                cTd[nb][kb + 1][c2i] = sc0.y; cTd[nb][kb + 1][c2i + 1] = sc0.y;
                cTd[nb][kb + 2][c2i] = sc0.z; cTd[nb][kb + 2][c2i + 1] = sc0.z;
                cTd[nb][kb + 3][c2i] = sc0.w; cTd[nb][kb + 3][c2i + 1] = sc0.w;
                cTd[nb][kb + 4][c2i] = sc1.x; cTd[nb][kb + 4][c2i + 1] = sc1.x;
                cTd[nb][kb + 5][c2i] = sc1.y; cTd[nb][kb + 5][c2i + 1] = sc1.y;
                cTd[nb][kb + 6][c2i] = sc1.z; cTd[nb][kb + 6][c2i + 1] = sc1.z;
                cTd[nb][kb + 7][c2i] = sc1.w; cTd[nb][kb + 7][c2i + 1] = sc1.w;
            }
            if (c + 2 < NCHUNK) {
                int k0 = (c + 2) * KCH;
                if (pload) {
#pragma unroll
                    for (int q = 0; q < 4; q++)
                        sp[q] = *(const float4 *)(prow + k0 + q * 4);
                }
                if (cload) {
                    sc0 = *(const float4 *)(crow + k0);
                    sc1 = *(const float4 *)(crow + k0 + 4);
                }
            }
        }
#pragma unroll
        for (int kk = 0; kk < KCH; ++kk) {
            ulonglong2 pa  = *(const ulonglong2 *)&pT[cur][kk][pc * 4];
            ulonglong2 c01 = *(const ulonglong2 *)&cTd[cur][kk][cc * 16 + 0];
            ulonglong2 c23 = *(const ulonglong2 *)&cTd[cur][kk][cc * 16 + 4];
            ulonglong2 c45 = *(const ulonglong2 *)&cTd[cur][kk][cc * 16 + 8];
            ulonglong2 c67 = *(const ulonglong2 *)&cTd[cur][kk][cc * 16 + 12];
            unsigned long long pp[2] = {pa.x, pa.y};
            unsigned long long cd[8] = {c01.x, c01.y, c23.x, c23.y,
                                        c45.x, c45.y, c67.x, c67.y};
#pragma unroll
            for (int i = 0; i < 2; i++)
#pragma unroll
                for (int j = 0; j < 8; j++)
                    acc[i][j] = fma2(pp[i], cd[j], acc[i][j]);
        }
        __syncthreads();
    }

    float c2s[8];
#pragma unroll
    for (int j = 0; j < 8; j++) c2s[j] = g_c2[r * 64 + cc * 8 + j];
#pragma unroll
    for (int e = 0; e < 4; ++e) {
        int pair = e >> 1, lane = e & 1;
        int p = pc * 4 + e;
        float x2v = g_x2[r * NP + pbase + p];
        float dots[8];
#pragma unroll
        for (int j = 0; j < 8; j++) {
            float lo, hi;
            unpack2(acc[pair][j], lo, hi);
            dots[j] = lane ? hi : lo;
        }
        float bv;
        int bj = 0;
        {
            float sS = __fadd_rn(x2v, c2s[0]);
            bv = __fadd_rn(sS, __fmul_rn(-2.f, dots[0]));
        }
#pragma unroll
        for (int j = 1; j < 8; j++) {
            float sS = __fadd_rn(x2v, c2s[j]);
            float v = __fadd_rn(sS, __fmul_rn(-2.f, dots[j]));
            if (v < bv) { bv = v; bj = j; }
        }
        rv[cc][p] = bv;
        ri[cc][p] = cc * 8 + bj;
    }
    __syncthreads();
    if (tid < 256) {
        float bv = rv[0][tid];
        int bi = ri[0][tid];
#pragma unroll
        for (int g = 1; g < 8; ++g) {
            float v = rv[g][tid];
            if (v < bv) { bv = v; bi = ri[g][tid]; }
        }
        g_labels[r * NP + pbase + tid] = bi;
        ri[0][tid] = bi;
    }
    if (write_out) {
        __syncthreads();
        int w = tid >> 5, lane = tid & 31;
#pragma unroll
        for (int i = 0; i < 16; ++i) {
            int row = w * 16 + i;
            int lb = ri[0][row];
            const float4 *src = (const float4 *)(g_centers + (((size_t)(r * 64 + lb)) << 10));
            float4 *dst = (float4 *)(out + (((size_t)(r * NP + pbase + row)) << 10));
#pragma unroll
            for (int j = 0; j < 8; ++j)
                dst[lane + 32 * j] = src[lane + 32 * j];
        }
    }
}

// -------- update: warp-scan compaction + sums + finalize --------
// block = (r, cluster c); 512 threads; labels read into regs; warp-shuffle scan.
// Member order: thread chunks of 8, tid ascending -> exact ascending-n (unchanged).
__global__ __launch_bounds__(512) void update_kernel(const float *__restrict__ x) {
    __shared__ int   mem[NP];       // 16 KB
    __shared__ int   warpTot[16];
    __shared__ float s2[SD];        // 4 KB
    int b = blockIdx.x;             // r*64 + c
    int r = b >> 6, c = b & 63, tid = threadIdx.x;
    int lane = tid & 31, wid = tid >> 5;

    // my 8 labels straight into registers
    int myl[8];
    {
        const int4 *lp = (const int4 *)&g_labels[r * NP + tid * 8];
        int4 a = lp[0], bb = lp[1];
        myl[0] = a.x;  myl[1] = a.y;  myl[2] = a.z;  myl[3] = a.w;
        myl[4] = bb.x; myl[5] = bb.y; myl[6] = bb.z; myl[7] = bb.w;
    }
    int k = 0;
#pragma unroll
    for (int i = 0; i < 8; ++i) k += (myl[i] == c);

    // warp inclusive scan
    int incl = k;
#pragma unroll
    for (int off = 1; off < 32; off <<= 1) {
        int nv = __shfl_up_sync(0xffffffffu, incl, off);
        if (lane >= off) incl += nv;
    }
    if (lane == 31) warpTot[wid] = incl;
    __syncthreads();
    int woff = 0, tot = 0;
#pragma unroll
    for (int w = 0; w < 16; ++w) {
        int v = warpTot[w];
        if (w < wid) woff += v;
        tot += v;
    }
    int pos = woff + incl - k;
    int base = tid * 8;
#pragma unroll
    for (int i = 0; i < 8; ++i) {
        if (myl[i] == c) mem[pos++] = base + i;
    }
    __syncthreads();

    int cnt = tot;
    size_t cbase = ((size_t)b) << 10;
    float ax = 0.f, ay = 0.f;
    const float *xr = x + ((size_t)r * NP) * SD;
    int d = tid * 2;
#pragma unroll 16
    for (int m = 0; m < cnt; ++m) {
        float2 v = *(const float2 *)(xr + ((size_t)mem[m]) * SD + d);
        ax = __fadd_rn(ax, v.x); ay = __fadd_rn(ay, v.y);
    }
    float fcnt = (float)cnt;
    float o0, o1;
    if (cnt > 0) {
        o0 = __fdiv_rn(ax, fcnt); o1 = __fdiv_rn(ay, fcnt);
    } else {
        o0 = g_centers[cbase + d + 0]; o1 = g_centers[cbase + d + 1];
    }
    g_centers[cbase + d + 0] = o0; g_centers[cbase + d + 1] = o1;
    s2[d + 0] = __fmul_rn(o0, o0); s2[d + 1] = __fmul_rn(o1, o1);
    __syncthreads();
    if (tid == 0) {
        float ss = 0.f;
#pragma unroll 8
        for (int dd = 0; dd < SD; ++dd) ss = __fadd_rn(ss, s2[dd]);
        g_c2[b] = ss;
    }
}

extern "C" void kernel_launch(void* const* d_in, const int* in_sizes, int n_in,
                              void* d_out, int out_size) {
    const float *x = (const float *)d_in[0];
    float *out = (float *)d_out;
    (void)in_sizes; (void)n_in; (void)out_size;

    init_gather_kernel<<<RG, 1024>>>(x);      // launch 1
    x2_kernel<<<RG * NP / 8, 128>>>(x);       // launch 2
    for (int it = 0; it < 10; ++it) {
        assign_kernel<<<RG * 16, 512>>>(x, out, 0);   // launch 3, 5, ...
        update_kernel<<<RG * LC, 512>>>(x);           // launch 4 <- profiled
    }
    assign_kernel<<<RG * 16, 512>>>(x, out, 1);
}